// round 17
// baseline (speedup 1.0000x reference)
#include <cuda_runtime.h>
#include <cuda_fp16.h>
#include <cstdint>

#define D1 200
#define NRELS 11
#define BATCHN 1024
#define NENT 100000
#define NENT_PAD 100096         // >= 1563 * 64
#define KPAD 208                // 13 k16 steps
#define KSTEPS 13
#define NTILES 1563             // n tiles of 64
#define MTILES 8                // m tiles of 128
#define ROWB 416                // KPAD * 2 bytes per gmem row

// ---------------- scratch (device globals; no allocation allowed) ----------------
__device__ __align__(16) float d_M[NRELS * D1 * D1];
__device__ __align__(16) float d_y[BATCHN * D1];
__device__ float d_stats[2 * D1];                  // BN1 sum / sumsq (atomics)
__device__ float d_bn0p[2 * 32 * D1];              // BN0 partials: 32 blocks x (sum|sumsq)

__device__ __align__(16) __half d_Af16[BATCHN * KPAD];
__device__ __align__(16) __half d_Ef16[(size_t)NENT_PAD * KPAD];

// ---------------- PTX helpers (generic-PTX-safe) ----------------
__device__ __forceinline__ uint32_t smem_u32(const void* p) {
    uint32_t a;
    asm("{ .reg .u64 t; cvta.to.shared.u64 t, %1; cvt.u32.u64 %0, t; }" : "=r"(a) : "l"(p));
    return a;
}
__device__ __forceinline__ void cp16(uint32_t dst, const void* src) {
    asm volatile("cp.async.cg.shared.global [%0], [%1], 16;" :: "r"(dst), "l"(src) : "memory");
}
__device__ __forceinline__ void cp_commit() { asm volatile("cp.async.commit_group;" ::: "memory"); }
template <int N>
__device__ __forceinline__ void cp_wait() { asm volatile("cp.async.wait_group %0;" :: "n"(N) : "memory"); }

__device__ __forceinline__ void ldx4(uint32_t& r0, uint32_t& r1, uint32_t& r2, uint32_t& r3,
                                     uint32_t addr) {
    asm volatile("ldmatrix.sync.aligned.m8n8.x4.shared.b16 {%0,%1,%2,%3}, [%4];"
                 : "=r"(r0), "=r"(r1), "=r"(r2), "=r"(r3) : "r"(addr));
}
__device__ __forceinline__ void mma16816h(float* c, const uint32_t* a, const uint32_t* b) {
    asm volatile(
        "mma.sync.aligned.m16n8k16.row.col.f32.f16.f16.f32 "
        "{%0,%1,%2,%3}, {%4,%5,%6,%7}, {%8,%9}, {%0,%1,%2,%3};"
        : "+f"(c[0]), "+f"(c[1]), "+f"(c[2]), "+f"(c[3])
        : "r"(a[0]), "r"(a[1]), "r"(a[2]), "r"(a[3]), "r"(b[0]), "r"(b[1]));
}

// ---------------- launch 1: mega-prep (independent block ranges) ----------------
#define NB_CONV 19532           // ceil(5,000,000 / 256)
#define NB_BN0  32
#define NB_BM   157             // ceil(40000 / 256)
#define NB_PREP (NB_CONV + NB_BN0 + NB_BM + 1)

__global__ void prep_kernel(const float* __restrict__ E, const int* __restrict__ e1_idx,
                            const float* __restrict__ R1, const float* __restrict__ R2,
                            const float* __restrict__ R3, const float* __restrict__ W1,
                            const float* __restrict__ W2, const float* __restrict__ W3) {
    const int bid = blockIdx.x;
    const int tid = threadIdx.x;

    if (bid < NB_CONV) {
        int f4 = bid * 256 + tid;                   // 5,000,000 float4s
        if (f4 >= (NENT * D1) / 4) return;
        int row = f4 / 50;                          // 50 float4 per row
        int col = (f4 - row * 50) * 4;
        float4 v = *(const float4*)(E + (size_t)f4 * 4);
        __half2 h01 = __floats2half2_rn(v.x, v.y);
        __half2 h23 = __floats2half2_rn(v.z, v.w);
        size_t o = (size_t)row * KPAD + col;
        *(__half2*)(d_Ef16 + o)     = h01;
        *(__half2*)(d_Ef16 + o + 2) = h23;
        return;
    }
    if (bid < NB_CONV + NB_BN0) {
        int b2 = bid - NB_CONV;                     // 0..31, covers 32 batch rows
        int j = tid;
        if (j >= D1) return;
        float s = 0.f, ss = 0.f;
#pragma unroll 8
        for (int r = 0; r < 32; r++) {
            int e1 = e1_idx[b2 * 32 + r];
            float v = E[e1 * D1 + j];
            s += v; ss += v * v;
        }
        d_bn0p[b2 * D1 + j] = s;
        d_bn0p[32 * D1 + b2 * D1 + j] = ss;
        return;
    }
    if (bid < NB_CONV + NB_BN0 + NB_BM) {
        int e = (bid - NB_CONV - NB_BN0) * 256 + tid;
        if (e >= D1 * D1) return;
        int j = e / D1, k = e % D1;
        int a = j < k ? j : k;
        int b = j < k ? k : j;
        int sidx = a * (2 * D1 - a + 1) / 2 + (b - a);
        float asign = 0.f; int aoff = 0;
        if (j < k)      { asign =  1.f; aoff = (2 * D1 - j - 1) * j / 2 + (k - j) - 1; }
        else if (j > k) { asign = -1.f; aoff = (2 * D1 - k - 1) * k / 2 + (j - k) - 1; }

        float m[NRELS];
#pragma unroll
        for (int r = 0; r < NRELS; r++) m[r] = 0.f;

#pragma unroll 5
        for (int s = 0; s < 30; s++) {
            float w1 = __ldg(W1 + s * 20100 + sidx);
            m[1]  = fmaf(__ldg(R1 + s),        w1, m[1]);
            m[8]  = fmaf(__ldg(R1 + 30 + s),   w1, m[8]);
            m[10] = fmaf(__ldg(R1 + 60 + s),   w1, m[10]);
            m[0]  = fmaf(__ldg(R3 + s),        w1, m[0]);
            m[3]  = fmaf(__ldg(R3 + 80 + s),   w1, m[3]);
            m[9]  = fmaf(__ldg(R3 + 160 + s),  w1, m[9]);
        }
        if (asign != 0.f) {
#pragma unroll 5
            for (int s = 0; s < 30; s++) {
                float w2 = asign * __ldg(W2 + s * 19900 + aoff);
                m[2] = fmaf(__ldg(R2 + s),        w2, m[2]);
                m[4] = fmaf(__ldg(R2 + 30 + s),   w2, m[4]);
                m[5] = fmaf(__ldg(R2 + 60 + s),   w2, m[5]);
                m[6] = fmaf(__ldg(R2 + 90 + s),   w2, m[6]);
                m[7] = fmaf(__ldg(R2 + 120 + s),  w2, m[7]);
                m[0] = fmaf(__ldg(R3 + 30 + s),   w2, m[0]);
                m[3] = fmaf(__ldg(R3 + 110 + s),  w2, m[3]);
                m[9] = fmaf(__ldg(R3 + 190 + s),  w2, m[9]);
            }
        }
#pragma unroll 5
        for (int o = 0; o < 20; o++) {
            float w3 = __ldg(W3 + o * 40000 + e);
            m[0] = fmaf(__ldg(R3 + 60 + o),   w3, m[0]);
            m[3] = fmaf(__ldg(R3 + 140 + o),  w3, m[3]);
            m[9] = fmaf(__ldg(R3 + 220 + o),  w3, m[9]);
        }
#pragma unroll
        for (int r = 0; r < NRELS; r++) d_M[r * 40000 + e] = m[r];
        return;
    }
    for (int t = tid; t < 2 * D1; t += 256) d_stats[t] = 0.f;
}

// ---------------- launch 2: y = M[r]^T bn0(E[e1]); BN1 atomics ----------------
__global__ void mid_kernel(const float* __restrict__ E, const int* __restrict__ e1_idx,
                           const int* __restrict__ r_idx,
                           const float* __restrict__ g0, const float* __restrict__ b0) {
    __shared__ float xs[D1];
    int b = blockIdx.x;
    int t = threadIdx.x;
    if (t < D1) {
        float s = 0.f, ss = 0.f;
#pragma unroll 8
        for (int i = 0; i < 32; i++) {
            s  += d_bn0p[i * D1 + t];
            ss += d_bn0p[32 * D1 + i * D1 + t];
        }
        float mean = s * (1.f / BATCHN);
        float var  = ss * (1.f / BATCHN) - mean * mean;
        float inv  = rsqrtf(var + 1e-5f);
        int e1 = e1_idx[b];
        xs[t] = (E[e1 * D1 + t] - mean) * inv * g0[t] + b0[t];
    }
    __syncthreads();
    if (t < D1) {
        const float* M = d_M + r_idx[b] * 40000;
        float acc0 = 0.f, acc1 = 0.f;
#pragma unroll 8
        for (int jj = 0; jj < D1; jj += 2) {
            acc0 = fmaf(M[jj * D1 + t],       xs[jj],     acc0);
            acc1 = fmaf(M[(jj + 1) * D1 + t], xs[jj + 1], acc1);
        }
        float acc = acc0 + acc1;
        d_y[b * D1 + t] = acc;
        atomicAdd(&d_stats[t], acc);
        atomicAdd(&d_stats[D1 + t], acc * acc);
    }
}

// ---------------- launch 3: BN1 + fp16 convert A ----------------
__global__ void bn1_convA_kernel(const float* __restrict__ g1, const float* __restrict__ b1) {
    int row = blockIdx.x;
    int col = threadIdx.x;
    if (col >= D1) return;
    float mean = d_stats[col] * (1.f / BATCHN);
    float var  = d_stats[D1 + col] * (1.f / BATCHN) - mean * mean;
    float inv  = rsqrtf(var + 1e-5f);
    float v = (d_y[row * D1 + col] - mean) * inv * g1[col] + b1[col];
    d_Af16[row * KPAD + col] = __float2half_rn(v);
}

// ---------------- sigmoid: FMUL + MUFU.EX2 + FADD + MUFU.RCP ----------------
__device__ __forceinline__ float sigmoidf_fast(float x) {
    float w = 1.0f + __expf(-x);
    float r;
    asm("rcp.approx.f32 %0, %1;" : "=f"(r) : "f"(w));
    return r;
}

// ---------------- launch 4: fp16 mma GEMM + sigmoid ----------------
// CTA 128x64, 256 threads / 8 warps (4m x 2n), warp tile 32x32, K = 13 x k16.
// __launch_bounds__(256, 4): 4 co-resident CTAs per SM = 4 independent barrier
// domains (occ 64%) so one CTA's MMA phase covers another's barrier/LDSM latency.
// smem per stage: A 128 rows x 48B = 6144B, B 64 rows x 48B = 3072B.
#define NSTAGE 5
#define MAT_A   6144
#define MAT_BB  3072
#define STAGE_B (MAT_A + MAT_BB)     // 9216
#define SMEM_GEMM (NSTAGE * STAGE_B) // 46080 (x4 CTAs = 184320 < 228KB)

__global__ __launch_bounds__(256, 4)
void gemm_mma_kernel(float* __restrict__ out) {
    extern __shared__ __align__(128) char smem[];
    const uint32_t sb = smem_u32(smem);
    const int tid  = threadIdx.x;
    const int lane = tid & 31;
    const int wid  = tid >> 5;
    const int wm   = wid >> 1;       // 0..3  (32 rows each)
    const int wn   = wid & 1;        // 0..1  (32 cols each)

    const int m0 = blockIdx.y << 7;
    const int n0 = blockIdx.x << 6;

    // ---- cp.async: every thread 1 A chunk; threads 128..255 also 1 B chunk ----
    const char* gA = (const char*)d_Af16 + (size_t)m0 * ROWB;
    const char* gB = (const char*)d_Ef16 + (size_t)n0 * ROWB;
    const int arow = tid >> 1, ahalf = tid & 1;
    const int bc   = tid - 128;      // valid when tid >= 128
    const int brow = bc >> 1, bhalf = bc & 1;

    auto issue = [&](int step, int slot) {
        uint32_t sbase = sb + slot * STAGE_B;
        cp16(sbase + arow * 48 + ahalf * 16,
             gA + (size_t)arow * ROWB + step * 32 + ahalf * 16);
        if (tid >= 128) {
            cp16(sbase + MAT_A + brow * 48 + bhalf * 16,
                 gB + (size_t)brow * ROWB + step * 32 + bhalf * 16);
        }
        cp_commit();
    };

    // ---- ldmatrix per-lane offsets (48B rows -> conflict-free) ----
    const int g  = lane >> 3;
    const int l8 = lane & 7;
    const uint32_t a_off = (uint32_t)((wm * 32 + (g & 1) * 8 + l8) * 48 + (g >> 1) * 16);
    const uint32_t b_off = (uint32_t)(MAT_A + (wn * 32 + (g >> 1) * 8 + l8) * 48 + (g & 1) * 16);

    float acc[2][4][4];
#pragma unroll
    for (int mi = 0; mi < 2; mi++)
#pragma unroll
        for (int ni = 0; ni < 4; ni++)
#pragma unroll
            for (int r = 0; r < 4; r++) acc[mi][ni][r] = 0.f;

    uint32_t ah[2][4], bh[4][2];

    auto load_frags = [&](int slot) {
        uint32_t base = sb + slot * STAGE_B;
#pragma unroll
        for (int mi = 0; mi < 2; mi++)
            ldx4(ah[mi][0], ah[mi][1], ah[mi][2], ah[mi][3], base + a_off + mi * 768);
#pragma unroll
        for (int p = 0; p < 2; p++)
            ldx4(bh[2*p][0], bh[2*p][1], bh[2*p+1][0], bh[2*p+1][1], base + b_off + p * 768);
    };

    auto do_mma = [&]() {
#pragma unroll
        for (int mi = 0; mi < 2; mi++)
#pragma unroll
            for (int ni = 0; ni < 4; ni++)
                mma16816h(acc[mi][ni], ah[mi], bh[ni]);
    };

    // ---- pipeline: prologue 4 stages, steady wait<3>, peeled tail; unrolled ----
    issue(0, 0); issue(1, 1); issue(2, 2); issue(3, 3);

#pragma unroll
    for (int i = 0; i < 10; i++) {
        cp_wait<3>();
        __syncthreads();
        load_frags(i % NSTAGE);
        if (i < 9) issue(i + 4, (i + 4) % NSTAGE);
        do_mma();
    }
    cp_wait<2>(); __syncthreads(); load_frags(10 % NSTAGE); do_mma();
    cp_wait<1>(); __syncthreads(); load_frags(11 % NSTAGE); do_mma();
    cp_wait<0>(); __syncthreads(); load_frags(12 % NSTAGE); do_mma();

    // ---- epilogue: sigmoid + float2 stores ----
    const int mrow0 = m0 + wm * 32 + (lane >> 2);
    const int ncol0 = n0 + wn * 32 + ((lane & 3) << 1);
#pragma unroll
    for (int mi = 0; mi < 2; mi++) {
#pragma unroll
        for (int ni = 0; ni < 4; ni++) {
            int gn = ncol0 + ni * 8;
            if (gn < NENT) {
                int gm = mrow0 + mi * 16;
                float2 v0, v1;
                v0.x = sigmoidf_fast(acc[mi][ni][0]);
                v0.y = sigmoidf_fast(acc[mi][ni][1]);
                v1.x = sigmoidf_fast(acc[mi][ni][2]);
                v1.y = sigmoidf_fast(acc[mi][ni][3]);
                *(float2*)(out + (size_t)gm * NENT + gn) = v0;
                *(float2*)(out + (size_t)(gm + 8) * NENT + gn) = v1;
            }
        }
    }
}

// ---------------- launch ----------------
extern "C" void kernel_launch(void* const* d_in, const int* in_sizes, int n_in,
                              void* d_out, int out_size) {
    const float* E  = (const float*)d_in[0];
    const float* R1 = (const float*)d_in[1];
    const float* R2 = (const float*)d_in[2];
    const float* R3 = (const float*)d_in[3];
    const float* W1 = (const float*)d_in[4];
    const float* W2 = (const float*)d_in[5];
    const float* W3 = (const float*)d_in[6];
    const float* g0 = (const float*)d_in[7];
    const float* b0 = (const float*)d_in[8];
    const float* g1 = (const float*)d_in[9];
    const float* b1 = (const float*)d_in[10];
    const int* e1_idx = (const int*)d_in[11];
    const int* r_idx  = (const int*)d_in[12];
    float* out = (float*)d_out;

    cudaFuncSetAttribute(gemm_mma_kernel, cudaFuncAttributeMaxDynamicSharedMemorySize,
                         SMEM_GEMM);

    prep_kernel<<<NB_PREP, 256>>>(E, e1_idx, R1, R2, R3, W1, W2, W3);   // 1
    mid_kernel<<<BATCHN, 256>>>(E, e1_idx, r_idx, g0, b0);              // 2
    bn1_convA_kernel<<<BATCHN, 256>>>(g1, b1);                          // 3
    gemm_mma_kernel<<<dim3(NTILES, MTILES), 256, SMEM_GEMM>>>(out);     // 4
}